// round 6
// baseline (speedup 1.0000x reference)
#include <cuda_runtime.h>

// Problem constants (fixed by dataset): B=1, N=4096, C=8, H=W=128, K=8
#define MAXN 8192
constexpr float RADIUS = 0.05f;
constexpr int H = 128, W = 128, C = 8, K = 8;
constexpr int TILE = 8;             // 8x8 pixel tiles
constexpr int TX = W / TILE;        // 16
constexpr int TY = H / TILE;        // 16
constexpr int NTILES = TX * TY;     // 256
constexpr int NBLK = NTILES;        // one block per tile
constexpr int PIX = TILE * TILE;    // 64 pixels
constexpr int SPLIT = 4;            // threads per pixel in scan phase
constexpr int TPB = PIX * SPLIT;    // 256 threads
constexpr int CAP = 512;            // per-tile bin capacity (expected ~52)
constexpr int LISTN = PIX * SPLIT * K;

// -------- global scratch (no cudaMalloc allowed) --------
__device__ int    g_cnt[NTILES];                 // zero-init; consumed via atomicExch
__device__ float4 g_bins[NTILES * CAP];

// -------- barrier state: every hot word on its own 128B line --------
constexpr int NLEAF = 8;
constexpr int LEAF_ARRIVALS = NBLK / NLEAF;      // 32
__device__ __align__(128) unsigned g_leaf[NLEAF * 32];   // use stride 32 (128B)
__device__ __align__(128) unsigned g_root;
__device__ __align__(128) unsigned g_release;            // monotonic epoch

__global__ void __launch_bounds__(TPB)
fused_kernel(const float* __restrict__ pts,
             const float* __restrict__ feat,
             float* __restrict__ out, int n) {
    __shared__ __align__(16) unsigned char raw[CAP * 16 + LISTN * 12];
    float4* s_cand = (float4*)raw;
    float*  s_mz   = (float*)(raw + CAP * 16);
    float*  s_md   = (float*)(raw + CAP * 16 + LISTN * 4);
    int*    s_mi   = (int*)  (raw + CAP * 16 + LISTN * 8);
    __shared__ int s_cnt;

    const int tile = blockIdx.x;
    const int tx = tile & (TX - 1);
    const int ty = tile >> 4;

    // ---------------- Phase A: bin points (each point handled exactly once) ---
    {
        int i = blockIdx.x * TPB + threadIdx.x;   // 65536 threads cover n<=8192
        if (i < n) {
            float x = pts[3 * i + 0];
            float y = pts[3 * i + 1];
            float z = pts[3 * i + 2];
            if (z > 0.0f) {
                float px = x / z;                  // exact IEEE, matches reference
                float py = y / z;
                // continuous pixel coordinate (pixel ix center at u = ix)
                float u = (px + 1.0f) * (0.5f * (float)W) - 0.5f;
                float v = (py + 1.0f) * (0.5f * (float)H) - 0.5f;
                const float PR = 3.25f;            // 3.2 px splat reach + eps
                int bx0 = max(0,      (int)floorf((u - PR) * (1.0f / TILE)));
                int bx1 = min(TX - 1, (int)floorf((u + PR) * (1.0f / TILE)));
                int by0 = max(0,      (int)floorf((v - PR) * (1.0f / TILE)));
                int by1 = min(TY - 1, (int)floorf((v + PR) * (1.0f / TILE)));
                if (bx0 <= bx1 && by0 <= by1) {
                    float4 rec = make_float4(px, py, z, __int_as_float(i));
                    for (int by = by0; by <= by1; by++)
                        for (int bx = bx0; bx <= bx1; bx++) {
                            int t = by * TX + bx;
                            int slot = atomicAdd(&g_cnt[t], 1);
                            if (slot < CAP) g_bins[t * CAP + slot] = rec;
                        }
                }
            }
        }
    }

    // ---------------- Global barrier: tree arrivals + backoff spin -----------
    __syncthreads();
    if (threadIdx.x == 0) {
        __threadfence();                                  // publish bin writes
        volatile unsigned* rel = &g_release;
        unsigned e0 = *rel;
        unsigned leaf = (blockIdx.x & (NLEAF - 1)) * 32;  // 128B-strided leaves
        if (atomicAdd(&g_leaf[leaf], 1u) == LEAF_ARRIVALS - 1) {
            g_leaf[leaf] = 0;                             // reset for next replay
            if (atomicAdd(&g_root, 1u) == NLEAF - 1) {
                g_root = 0;
                __threadfence();
                *rel = e0 + 1;                            // release everyone
            }
        }
        while (*rel == e0) __nanosleep(64);
    }
    __syncthreads();

    // ---------------- Phase B: render this tile ------------------------------
    // consume-and-reset count (atomicExch keeps graph replays clean)
    if (threadIdx.x == 0) s_cnt = atomicExch(&g_cnt[tile], 0);
    __syncthreads();
    const int cnt = min(s_cnt, CAP);

    // stage candidates into smem (cnt ~ 52 -> one iteration)
    for (int j = threadIdx.x; j < cnt; j += TPB)
        s_cand[j] = g_bins[tile * CAP + j];
    __syncthreads();

    const int p = threadIdx.x >> 2;        // pixel 0..63
    const int s = threadIdx.x & 3;         // sub-lane 0..3
    const int lx = p & (TILE - 1);
    const int ly = p >> 3;
    const int ix = tx * TILE + lx;
    const int iy = ty * TILE + ly;

    const float gx = ((float)ix + 0.5f) * (2.0f / W) - 1.0f;
    const float gy = ((float)iy + 0.5f) * (2.0f / H) - 1.0f;
    const float r2 = RADIUS * RADIUS;

    float lz[K], ld[K];
    int   li[K];
    #pragma unroll
    for (int k = 0; k < K; k++) { lz[k] = 3.0e38f; ld[k] = 0.0f; li[k] = 0; }

    for (int j = s; j < cnt; j += SPLIT) {
        float4 c = s_cand[j];
        float dx = gx - c.x;
        float dy = gy - c.y;
        float d2 = dx * dx + dy * dy;
        // distinct depths -> top-K set is order-independent (matches top_k)
        if (d2 < r2 && c.z < lz[K - 1]) {
            lz[K - 1] = c.z; ld[K - 1] = d2; li[K - 1] = __float_as_int(c.w);
            #pragma unroll
            for (int k = K - 1; k > 0; k--) {
                if (lz[k] < lz[k - 1]) {
                    float t0 = lz[k]; lz[k] = lz[k - 1]; lz[k - 1] = t0;
                    float t1 = ld[k]; ld[k] = ld[k - 1]; ld[k - 1] = t1;
                    int   t2 = li[k]; li[k] = li[k - 1]; li[k - 1] = t2;
                }
            }
        }
    }

    // publish local sorted top-8 lists
    {
        int off = (p * SPLIT + s) * K;
        #pragma unroll
        for (int k = 0; k < K; k++) {
            s_mz[off + k] = lz[k];
            s_md[off + k] = ld[k];
            s_mi[off + k] = li[k];
        }
    }
    __syncthreads();

    // 4-way merge + composite + store (one thread per pixel)
    if (s == 0) {
        int   hp[SPLIT];
        float hz[SPLIT];
        #pragma unroll
        for (int q = 0; q < SPLIT; q++) {
            hp[q] = (p * SPLIT + q) * K;
            hz[q] = s_mz[hp[q]];
        }

        float acc[C];
        #pragma unroll
        for (int c = 0; c < C; c++) acc[c] = 0.0f;
        float T = 1.0f;
        const float inv_r2 = 1.0f / r2;

        #pragma unroll
        for (int k = 0; k < K; k++) {
            int b = 0;
            if (hz[1] < hz[b]) b = 1;
            if (hz[2] < hz[b]) b = 2;
            if (hz[3] < hz[b]) b = 3;
            float zk = hz[b];
            if (zk < 1.0e38f) {
                float d2 = s_md[hp[b]];
                int   id = s_mi[hp[b]];
                float a = 1.0f - d2 * inv_r2;
                a = fminf(fmaxf(a, 0.0f), 1.0f);
                float w = a * T;
                const float4* f = (const float4*)(feat + (size_t)id * C);
                float4 f0 = __ldg(&f[0]);
                float4 f1 = __ldg(&f[1]);
                acc[0] += w * f0.x; acc[1] += w * f0.y;
                acc[2] += w * f0.z; acc[3] += w * f0.w;
                acc[4] += w * f1.x; acc[5] += w * f1.y;
                acc[6] += w * f1.z; acc[7] += w * f1.w;
                T *= (1.0f - a);
            }
            hp[b]++;
            hz[b] = ((hp[b] & (K - 1)) != 0) ? s_mz[hp[b]] : 3.0e38f;
        }

        float4* o = (float4*)(out + (size_t)(iy * W + ix) * C);
        o[0] = make_float4(acc[0], acc[1], acc[2], acc[3]);
        o[1] = make_float4(acc[4], acc[5], acc[6], acc[7]);
    }
}

extern "C" void kernel_launch(void* const* d_in, const int* in_sizes, int n_in,
                              void* d_out, int out_size) {
    const float* pts  = (const float*)d_in[0];   // [B,N,3] f32
    const float* feat = (const float*)d_in[1];   // [B,N,C] f32
    float* out = (float*)d_out;                  // [B,H,W,C] f32
    int n = in_sizes[0] / 3;                     // B=1 -> N
    if (n > MAXN) n = MAXN;

    fused_kernel<<<NBLK, TPB>>>(pts, feat, out, n);
}